// round 1
// baseline (speedup 1.0000x reference)
#include <cuda_runtime.h>
#include <cuda_bf16.h>
#include <cstdint>

// ---------------- problem constants ----------------
#define E_DIM   768
#define B_SZ    8
#define NQ      8192          // 8 * 32 * 32 queries
#define NBANK   20000
#define NPAD    20096         // 157 * 128
#define OUTS    512

// ---------------- GEMM tiling ----------------
#define M_TILE  128
#define N_TILE  128
#define K_TILE  32
#define KS      40            // smem row stride in halves (conflict-free for ldmatrix)
#define NSPLITS 4
#define NTILES  157           // NPAD / N_TILE
#define KITERS  (E_DIM / K_TILE)   // 24

// ---------------- device scratch (no allocations allowed) ----------------
__device__ __align__(256) __nv_bfloat16 g_q[NQ * E_DIM];                 // 12.6 MB
__device__ __align__(256) __nv_bfloat16 g_bank[(size_t)NPAD * E_DIM];    // 30.9 MB
__device__ float g_q2[NQ];
__device__ float g_b2[NPAD];
__device__ float g_part[NQ * NSPLITS * 3];
__device__ float g_scores[NQ];

// ---------------- PTX helpers ----------------
__device__ __forceinline__ void cp_async16(uint32_t dst, const void* src) {
    asm volatile("cp.async.cg.shared.global [%0], [%1], 16;\n" :: "r"(dst), "l"(src));
}
__device__ __forceinline__ void cp_commit() { asm volatile("cp.async.commit_group;\n"); }
__device__ __forceinline__ void cp_wait1()  { asm volatile("cp.async.wait_group 1;\n"); }
__device__ __forceinline__ void cp_wait0()  { asm volatile("cp.async.wait_group 0;\n"); }

#define LDM4(r0, r1, r2, r3, addr)                                          \
    asm volatile("ldmatrix.sync.aligned.m8n8.x4.shared.b16 {%0,%1,%2,%3}, [%4];" \
                 : "=r"(r0), "=r"(r1), "=r"(r2), "=r"(r3) : "r"(addr))

#define MMA16816(c, a, b)                                                    \
    asm volatile("mma.sync.aligned.m16n8k16.row.col.f32.bf16.bf16.f32 "      \
                 "{%0,%1,%2,%3},{%4,%5,%6,%7},{%8,%9},{%0,%1,%2,%3};"        \
                 : "+f"(c[0]), "+f"(c[1]), "+f"(c[2]), "+f"(c[3])            \
                 : "r"(a[0]), "r"(a[1]), "r"(a[2]), "r"(a[3]),               \
                   "r"(b[0]), "r"(b[1]))

__device__ __forceinline__ void upd3(float* t, float v) {
    if (v < t[2]) {
        if (v < t[1]) {
            t[2] = t[1];
            if (v < t[0]) { t[1] = t[0]; t[0] = v; } else t[1] = v;
        } else t[2] = v;
    }
}

// ---------------- prep: bank -> bf16 + ||b||^2 (warp per row) ----------------
__global__ void prep_bank_kernel(const float* __restrict__ bank) {
    int w = threadIdx.x >> 5, lane = threadIdx.x & 31;
    int n = blockIdx.x * 8 + w;
    if (n >= NPAD) return;
    float ss = 0.f;
    __nv_bfloat16* dst = g_bank + (size_t)n * E_DIM;
    if (n < NBANK) {
        const float* src = bank + (size_t)n * E_DIM;
        #pragma unroll
        for (int e = lane; e < E_DIM; e += 32) {
            float v = src[e];
            ss = fmaf(v, v, ss);
            dst[e] = __float2bfloat16(v);
        }
    } else {
        for (int e = lane; e < E_DIM; e += 32) dst[e] = __float2bfloat16(0.f);
    }
    #pragma unroll
    for (int o = 16; o; o >>= 1) ss += __shfl_xor_sync(0xffffffffu, ss, o);
    if (lane == 0) g_b2[n] = (n < NBANK) ? ss : 1e30f;
}

// ---------------- prep: embeddings [B,E,H,W] -> q[B*HW][E] bf16 + ||q||^2 ----------------
__global__ void prep_q_kernel(const float* __restrict__ emb) {
    int w = threadIdx.x >> 5, lane = threadIdx.x & 31;
    int q = blockIdx.x * 8 + w;             // 0..8191
    int b = q >> 10, hw = q & 1023;
    const float* src = emb + (size_t)b * E_DIM * 1024 + hw;
    __nv_bfloat16* dst = g_q + (size_t)q * E_DIM;
    float ss = 0.f;
    #pragma unroll
    for (int e = lane; e < E_DIM; e += 32) {
        float v = src[(size_t)e * 1024];
        ss = fmaf(v, v, ss);
        dst[e] = __float2bfloat16(v);
    }
    #pragma unroll
    for (int o = 16; o; o >>= 1) ss += __shfl_xor_sync(0xffffffffu, ss, o);
    if (lane == 0) g_q2[q] = ss;
}

// ---------------- main: fused bf16 GEMM + top-3 (values only) ----------------
__global__ __launch_bounds__(256, 1) void knn_main_kernel() {
    extern __shared__ __align__(16) unsigned char smem_raw[];
    // layout (bytes): sQ stage0 [10240], sQ stage1, sB stage0, sB stage1, b2s[128] floats
    const int STAGE_B = M_TILE * KS * 2;  // 10240 bytes per stage
    uint32_t smem_base = (uint32_t)__cvta_generic_to_shared(smem_raw);
    float* b2s = (float*)(smem_raw + 4 * STAGE_B);

    int tid = threadIdx.x;
    int warp = tid >> 5, lane = tid & 31;
    int wm = warp >> 1, wn = warp & 1;     // 4x2 warp grid: 32 rows x 64 cols each
    int g = lane >> 2, tg = lane & 3;
    int mtile = blockIdx.x, split = blockIdx.y;
    int t0 = (NTILES * split) / NSPLITS;
    int t1 = (NTILES * (split + 1)) / NSPLITS;

    // cp.async chunk mapping: 512 chunks of 16B per tile operand; thread does tid, tid+256
    int r0c = tid >> 2, u0 = tid & 3;
    int r1c = 64 + (tid >> 2);

    // ldmatrix per-lane addressing (matrix id from lane>>3)
    int m_id = lane >> 3, rr = lane & 7;
    int a_row = wm * 32 + (m_id & 1) * 8 + rr;
    int a_cb  = (m_id >> 1) * 8;
    int b_row = wn * 64 + (m_id >> 1) * 8 + rr;
    int b_cb  = (m_id & 1) * 8;

    float top3[4][3];
    #pragma unroll
    for (int j = 0; j < 4; j++)
        #pragma unroll
        for (int k = 0; k < 3; k++) top3[j][k] = 1e30f;

    const __nv_bfloat16* Qg = g_q + (size_t)mtile * M_TILE * E_DIM;

    for (int tile = t0; tile < t1; tile++) {
        int nb = tile * N_TILE;
        const __nv_bfloat16* Bg = g_bank + (size_t)nb * E_DIM;
        __syncthreads();                   // previous epilogue done with b2s / smem
        if (tid < N_TILE) b2s[tid] = g_b2[nb + tid];

        float acc[2][8][4];
        #pragma unroll
        for (int mi = 0; mi < 2; mi++)
            #pragma unroll
            for (int ni = 0; ni < 8; ni++)
                #pragma unroll
                for (int k = 0; k < 4; k++) acc[mi][ni][k] = 0.f;

        // prologue: stage 0 <- k-iter 0
        cp_async16(smem_base + 0 * STAGE_B + r0c * 80 + u0 * 16, Qg + r0c * E_DIM + u0 * 8);
        cp_async16(smem_base + 0 * STAGE_B + r1c * 80 + u0 * 16, Qg + r1c * E_DIM + u0 * 8);
        cp_async16(smem_base + 2 * STAGE_B + r0c * 80 + u0 * 16, Bg + r0c * E_DIM + u0 * 8);
        cp_async16(smem_base + 2 * STAGE_B + r1c * 80 + u0 * 16, Bg + r1c * E_DIM + u0 * 8);
        cp_commit();

        for (int kit = 0; kit < KITERS; kit++) {
            int st = kit & 1;
            if (kit + 1 < KITERS) {
                int k0 = (kit + 1) * K_TILE;
                int st2 = (kit + 1) & 1;
                cp_async16(smem_base + st2 * STAGE_B + r0c * 80 + u0 * 16, Qg + r0c * E_DIM + k0 + u0 * 8);
                cp_async16(smem_base + st2 * STAGE_B + r1c * 80 + u0 * 16, Qg + r1c * E_DIM + k0 + u0 * 8);
                cp_async16(smem_base + (2 + st2) * STAGE_B + r0c * 80 + u0 * 16, Bg + r0c * E_DIM + k0 + u0 * 8);
                cp_async16(smem_base + (2 + st2) * STAGE_B + r1c * 80 + u0 * 16, Bg + r1c * E_DIM + k0 + u0 * 8);
                cp_commit();
                cp_wait1();
            } else {
                cp_wait0();
            }
            __syncthreads();

            uint32_t qb = smem_base + st * STAGE_B;
            uint32_t bb = smem_base + (2 + st) * STAGE_B;
            #pragma unroll
            for (int ks = 0; ks < 2; ks++) {
                uint32_t a[2][4];
                #pragma unroll
                for (int mi = 0; mi < 2; mi++) {
                    uint32_t addr = qb + (uint32_t)((a_row + mi * 16) * 80 + (ks * 16 + a_cb) * 2);
                    LDM4(a[mi][0], a[mi][1], a[mi][2], a[mi][3], addr);
                }
                uint32_t bf[8][2];
                #pragma unroll
                for (int nj = 0; nj < 4; nj++) {
                    uint32_t addr = bb + (uint32_t)((b_row + nj * 16) * 80 + (ks * 16 + b_cb) * 2);
                    LDM4(bf[2 * nj][0], bf[2 * nj][1], bf[2 * nj + 1][0], bf[2 * nj + 1][1], addr);
                }
                #pragma unroll
                for (int mi = 0; mi < 2; mi++)
                    #pragma unroll
                    for (int ni = 0; ni < 8; ni++)
                        MMA16816(acc[mi][ni], a[mi], bf[ni]);
            }
            __syncthreads();               // protect stage before it is overwritten
        }

        // epilogue: rank (b2 - 2*dot); q2 added in finalize (constant per row)
        #pragma unroll
        for (int mi = 0; mi < 2; mi++) {
            #pragma unroll
            for (int ni = 0; ni < 8; ni++) {
                int cb = wn * 64 + ni * 8 + tg * 2;
                float b2a = b2s[cb], b2b = b2s[cb + 1];
                upd3(top3[mi * 2],     fmaf(-2.f, acc[mi][ni][0], b2a));
                upd3(top3[mi * 2],     fmaf(-2.f, acc[mi][ni][1], b2b));
                upd3(top3[mi * 2 + 1], fmaf(-2.f, acc[mi][ni][2], b2a));
                upd3(top3[mi * 2 + 1], fmaf(-2.f, acc[mi][ni][3], b2b));
            }
        }
    }

    // merge 8 partial top-3s per row via smem (reuse pipeline smem)
    __syncthreads();
    float* mrg = (float*)smem_raw;         // 128 rows * 8 slots * 3 = 12 KB
    int slot = wn * 4 + tg;
    #pragma unroll
    for (int j = 0; j < 4; j++) {
        int row = wm * 32 + (j >> 1) * 16 + (j & 1) * 8 + g;
        #pragma unroll
        for (int k = 0; k < 3; k++) mrg[(row * 8 + slot) * 3 + k] = top3[j][k];
    }
    __syncthreads();
    if (tid < M_TILE) {
        float t0v = 1e30f, t1v = 1e30f, t2v = 1e30f;
        const float* p = mrg + tid * 24;
        #pragma unroll
        for (int i = 0; i < 24; i++) {
            float v = p[i];
            if (v < t2v) {
                if (v < t1v) { t2v = t1v; if (v < t0v) { t1v = t0v; t0v = v; } else t1v = v; }
                else t2v = v;
            }
        }
        int q = mtile * M_TILE + tid;
        float* o = g_part + (q * NSPLITS + split) * 3;
        o[0] = t0v; o[1] = t1v; o[2] = t2v;
    }
}

// ---------------- finalize: merge splits, sqrt-mean ----------------
__global__ void finalize_kernel() {
    int q = blockIdx.x * blockDim.x + threadIdx.x;
    if (q >= NQ) return;
    float t0 = 1e30f, t1 = 1e30f, t2 = 1e30f;
    const float* p = g_part + q * NSPLITS * 3;
    #pragma unroll
    for (int i = 0; i < NSPLITS * 3; i++) {
        float v = p[i];
        if (v < t2) {
            if (v < t1) { t2 = t1; if (v < t0) { t1 = t0; t0 = v; } else t1 = v; }
            else t2 = v;
        }
    }
    float q2 = g_q2[q];
    float s = (sqrtf(fmaxf(q2 + t0, 1e-12f)) +
               sqrtf(fmaxf(q2 + t1, 1e-12f)) +
               sqrtf(fmaxf(q2 + t2, 1e-12f))) * (1.f / 3.f);
    g_scores[q] = s;
}

// ---------------- bilinear 32 -> 512 (half-pixel, clamped) ----------------
__global__ void resize_kernel(float* __restrict__ out) {
    int idx = blockIdx.x * 256 + threadIdx.x;
    if (idx >= B_SZ * OUTS * OUTS) return;
    int x = idx & (OUTS - 1);
    int y = (idx >> 9) & (OUTS - 1);
    int b = idx >> 18;
    float sx = (x + 0.5f) * (1.0f / 16.0f) - 0.5f;
    float sy = (y + 0.5f) * (1.0f / 16.0f) - 0.5f;
    float fx0 = floorf(sx), fy0 = floorf(sy);
    float ax = sx - fx0, ay = sy - fy0;
    int ix0 = (int)fx0, iy0 = (int)fy0;
    int x0 = max(0, min(31, ix0)),     x1 = max(0, min(31, ix0 + 1));
    int y0 = max(0, min(31, iy0)),     y1 = max(0, min(31, iy0 + 1));
    const float* s = g_scores + b * 1024;
    float v00 = s[y0 * 32 + x0], v01 = s[y0 * 32 + x1];
    float v10 = s[y1 * 32 + x0], v11 = s[y1 * 32 + x1];
    float v0 = v00 + ax * (v01 - v00);
    float v1 = v10 + ax * (v11 - v10);
    out[idx] = v0 + ay * (v1 - v0);
}

// ---------------- launch ----------------
extern "C" void kernel_launch(void* const* d_in, const int* in_sizes, int n_in,
                              void* d_out, int out_size) {
    const float* emb  = (const float*)d_in[0];
    const float* bank = (n_in > 1) ? (const float*)d_in[1] : nullptr;
    for (int i = 0; i < n_in; i++) {
        if (in_sizes[i] == B_SZ * E_DIM * 32 * 32) emb  = (const float*)d_in[i];
        else if (in_sizes[i] == NBANK * E_DIM)     bank = (const float*)d_in[i];
    }

    prep_bank_kernel<<<NPAD / 8, 256>>>(bank);
    prep_q_kernel<<<NQ / 8, 256>>>(emb);

    dim3 grid(NQ / M_TILE, NSPLITS);   // 64 x 4
    size_t smem_bytes = 4 * (size_t)(M_TILE * KS * 2) + N_TILE * sizeof(float);  // 41472 < 48K
    knn_main_kernel<<<grid, 256, smem_bytes>>>();

    finalize_kernel<<<NQ / 256, 256>>>();
    resize_kernel<<<(B_SZ * OUTS * OUTS) / 256, 256>>>((float*)d_out);
}